// round 8
// baseline (speedup 1.0000x reference)
#include <cuda_runtime.h>
#include <cuda_bf16.h>
#include <math.h>
#include <stdint.h>

// ---------------------------------------------------------------------------
// Problem constants
// ---------------------------------------------------------------------------
#define D_MODEL 1024
#define NHEAD   16
#define HEAD_DIM 64
#define DIM_FF  4096
#define BATCH   4
#define TC      1024
#define TP      1024
#define TK      2048
#define NROWS   (BATCH * TC)    // 4096
#define EPSF    1e-5f

// ---------------------------------------------------------------------------
// Scratch (device globals; no allocations allowed)
// ---------------------------------------------------------------------------
__device__ float          g_x1   [(size_t)NROWS * D_MODEL];
__device__ __nv_bfloat16  g_h_hi [(size_t)NROWS * D_MODEL];
__device__ __nv_bfloat16  g_h_lo [(size_t)NROWS * D_MODEL];
__device__ __nv_bfloat16  g_q_hi [(size_t)NROWS * D_MODEL];
__device__ __nv_bfloat16  g_q_lo [(size_t)NROWS * D_MODEL];
__device__ __nv_bfloat16  g_o_hi [(size_t)NROWS * D_MODEL];
__device__ __nv_bfloat16  g_o_lo [(size_t)NROWS * D_MODEL];
__device__ __nv_bfloat16  g_h2_hi[(size_t)NROWS * D_MODEL];
__device__ __nv_bfloat16  g_h2_lo[(size_t)NROWS * D_MODEL];
__device__ __nv_bfloat16  g_ff_hi[(size_t)NROWS * DIM_FF];
__device__ __nv_bfloat16  g_ff_lo[(size_t)NROWS * DIM_FF];
// bf16 split K/V caches for tensor-core attention
__device__ __nv_bfloat16  g_Kbh[(size_t)BATCH * NHEAD * TK * HEAD_DIM];
__device__ __nv_bfloat16  g_Kbl[(size_t)BATCH * NHEAD * TK * HEAD_DIM];
__device__ __nv_bfloat16  g_Vbh[(size_t)BATCH * NHEAD * TK * HEAD_DIM];
__device__ __nv_bfloat16  g_Vbl[(size_t)BATCH * NHEAD * TK * HEAD_DIM];
// transposed-split weights [N,K]
__device__ __nv_bfloat16  g_wqkvT_hi[(size_t)3 * D_MODEL * D_MODEL];
__device__ __nv_bfloat16  g_wqkvT_lo[(size_t)3 * D_MODEL * D_MODEL];
__device__ __nv_bfloat16  g_woT_hi  [(size_t)D_MODEL * D_MODEL];
__device__ __nv_bfloat16  g_woT_lo  [(size_t)D_MODEL * D_MODEL];
__device__ __nv_bfloat16  g_w1T_hi  [(size_t)DIM_FF * D_MODEL];
__device__ __nv_bfloat16  g_w1T_lo  [(size_t)DIM_FF * D_MODEL];
__device__ __nv_bfloat16  g_w2T_hi  [(size_t)D_MODEL * DIM_FF];
__device__ __nv_bfloat16  g_w2T_lo  [(size_t)D_MODEL * DIM_FF];

// ---------------------------------------------------------------------------
// Helpers
// ---------------------------------------------------------------------------
__device__ __forceinline__ uint32_t s2u(const void* p) {
    uint32_t a;
    asm("{ .reg .u64 t; cvta.to.shared.u64 t, %1; cvt.u32.u64 %0, t; }" : "=r"(a) : "l"(p));
    return a;
}
__device__ __forceinline__ void cp16(uint32_t dst, const void* src) {
    asm volatile("cp.async.cg.shared.global [%0], [%1], 16;" :: "r"(dst), "l"(src));
}
#define CP_COMMIT() asm volatile("cp.async.commit_group;" ::: "memory")
#define CP_WAIT(n)  asm volatile("cp.async.wait_group %0;" :: "n"(n) : "memory")

__device__ __forceinline__ void ldsm4(uint32_t* r, uint32_t addr) {
    asm volatile("ldmatrix.sync.aligned.m8n8.x4.shared.b16 {%0,%1,%2,%3}, [%4];"
                 : "=r"(r[0]), "=r"(r[1]), "=r"(r[2]), "=r"(r[3]) : "r"(addr));
}
__device__ __forceinline__ void ldsm4t(uint32_t* r, uint32_t addr) {
    asm volatile("ldmatrix.sync.aligned.m8n8.x4.trans.shared.b16 {%0,%1,%2,%3}, [%4];"
                 : "=r"(r[0]), "=r"(r[1]), "=r"(r[2]), "=r"(r[3]) : "r"(addr));
}
__device__ __forceinline__ void mma16816(float* d, const uint32_t* a, const uint32_t* b) {
    asm volatile(
        "mma.sync.aligned.m16n8k16.row.col.f32.bf16.bf16.f32 "
        "{%0,%1,%2,%3}, {%4,%5,%6,%7}, {%8,%9}, {%0,%1,%2,%3};"
        : "+f"(d[0]), "+f"(d[1]), "+f"(d[2]), "+f"(d[3])
        : "r"(a[0]), "r"(a[1]), "r"(a[2]), "r"(a[3]), "r"(b[0]), "r"(b[1]));
}
__device__ __forceinline__ void packsplit(float v0, float v1, uint32_t& hi, uint32_t& lo) {
    __nv_bfloat16 h0 = __float2bfloat16(v0), h1 = __float2bfloat16(v1);
    __nv_bfloat16 l0 = __float2bfloat16(v0 - __bfloat162float(h0));
    __nv_bfloat16 l1 = __float2bfloat16(v1 - __bfloat162float(h1));
    __nv_bfloat162 H(h0, h1), L(l0, l1);
    hi = *(uint32_t*)&H; lo = *(uint32_t*)&L;
}

// ---------------------------------------------------------------------------
// LayerNorm -> split bf16 hi/lo
// ---------------------------------------------------------------------------
__global__ void ln_split_kernel(const float* __restrict__ x, const float* __restrict__ g,
                                const float* __restrict__ be,
                                __nv_bfloat16* __restrict__ hi, __nv_bfloat16* __restrict__ lo) {
    __shared__ float red[16];
    __shared__ float s_mu, s_rstd;
    const int row = blockIdx.x;
    const int tid = threadIdx.x;
    const float4 v = ((const float4*)(x + (size_t)row * D_MODEL))[tid];
    float s  = v.x + v.y + v.z + v.w;
    float sq = fmaf(v.x, v.x, fmaf(v.y, v.y, fmaf(v.z, v.z, v.w * v.w)));
#pragma unroll
    for (int o = 16; o; o >>= 1) {
        s  += __shfl_xor_sync(0xFFFFFFFFu, s, o);
        sq += __shfl_xor_sync(0xFFFFFFFFu, sq, o);
    }
    const int w = tid >> 5, lane = tid & 31;
    if (lane == 0) { red[w] = s; red[w + 8] = sq; }
    __syncthreads();
    if (tid == 0) {
        float S = 0.f, Q = 0.f;
#pragma unroll
        for (int i = 0; i < 8; i++) { S += red[i]; Q += red[i + 8]; }
        float mu  = S * (1.f / D_MODEL);
        float var = Q * (1.f / D_MODEL) - mu * mu;
        s_mu = mu; s_rstd = rsqrtf(var + EPSF);
    }
    __syncthreads();
    const float mu = s_mu, rstd = s_rstd;
    const float4 gv = ((const float4*)g)[tid];
    const float4 bv = ((const float4*)be)[tid];
    float o4[4];
    o4[0] = (v.x - mu) * rstd * gv.x + bv.x;
    o4[1] = (v.y - mu) * rstd * gv.y + bv.y;
    o4[2] = (v.z - mu) * rstd * gv.z + bv.z;
    o4[3] = (v.w - mu) * rstd * gv.w + bv.w;
    __nv_bfloat162* hp = (__nv_bfloat162*)(hi + (size_t)row * D_MODEL) + tid * 2;
    __nv_bfloat162* lp = (__nv_bfloat162*)(lo + (size_t)row * D_MODEL) + tid * 2;
#pragma unroll
    for (int j = 0; j < 2; j++) {
        uint32_t h, l;
        packsplit(o4[2 * j], o4[2 * j + 1], h, l);
        hp[j] = *(__nv_bfloat162*)&h;
        lp[j] = *(__nv_bfloat162*)&l;
    }
}

// ---------------------------------------------------------------------------
// All-weights transpose + split in one launch.
// tiles: wqkv 96x32=3072 | wo 32x32=1024 | w1 128x32=4096 | w2 32x128=4096
// ---------------------------------------------------------------------------
__global__ void transpose_all(const float* __restrict__ wqkv, const float* __restrict__ wo,
                              const float* __restrict__ w1, const float* __restrict__ w2) {
    __shared__ float t[32][33];
    const int bid = blockIdx.x;
    const float* W; __nv_bfloat16 *hi, *lo; int K, N, base;
    if (bid < 3072)      { W = wqkv; hi = g_wqkvT_hi; lo = g_wqkvT_lo; K = 1024; N = 3072; base = bid; }
    else if (bid < 4096) { W = wo;   hi = g_woT_hi;   lo = g_woT_lo;   K = 1024; N = 1024; base = bid - 3072; }
    else if (bid < 8192) { W = w1;   hi = g_w1T_hi;   lo = g_w1T_lo;   K = 1024; N = 4096; base = bid - 4096; }
    else                 { W = w2;   hi = g_w2T_hi;   lo = g_w2T_lo;   K = 4096; N = 1024; base = bid - 8192; }
    const int ntN = N >> 5;
    const int n0 = (base % ntN) * 32, k0 = (base / ntN) * 32;
    const int tx = threadIdx.x & 31, ty = threadIdx.x >> 5;
#pragma unroll
    for (int i = 0; i < 32; i += 8)
        t[ty + i][tx] = W[(size_t)(k0 + ty + i) * N + n0 + tx];
    __syncthreads();
#pragma unroll
    for (int i = 0; i < 32; i += 8) {
        float v = t[tx][ty + i];
        __nv_bfloat16 h = __float2bfloat16(v);
        __nv_bfloat16 l = __float2bfloat16(v - __bfloat162float(h));
        hi[(size_t)(n0 + ty + i) * K + k0 + tx] = h;
        lo[(size_t)(n0 + ty + i) * K + k0 + tx] = l;
    }
}

// ---------------------------------------------------------------------------
// KV prefix copy: Kp/Vp (t < TP) -> fp32 caches + bf16 splits
// ---------------------------------------------------------------------------
__global__ void kv_prefix(const float* __restrict__ Kp, const float* __restrict__ Vp,
                          float* __restrict__ outK, float* __restrict__ outV) {
    const size_t PER = (size_t)BATCH * NHEAD * TP * HEAD_DIM / 4;  // 1,048,576
    size_t i = (size_t)blockIdx.x * blockDim.x + threadIdx.x;
    if (i >= 2 * PER) return;
    const int which = i >= PER;
    const size_t j = which ? (i - PER) : i;
    const size_t srow = j >> 4;           // bh*TP + t
    const int d4 = (int)(j & 15);
    const size_t bh = srow >> 10;
    const int t = (int)(srow & (TP - 1));
    const float4 v = ((const float4*)(which ? Vp : Kp))[srow * 16 + d4];
    const size_t drow = bh * TK + t;
    ((float4*)(which ? outV : outK))[drow * 16 + d4] = v;
    uint32_t h01, l01, h23, l23;
    packsplit(v.x, v.y, h01, l01);
    packsplit(v.z, v.w, h23, l23);
    const size_t eb = drow * 64 + (size_t)d4 * 4;
    __nv_bfloat162* Hp = (__nv_bfloat162*)((which ? g_Vbh : g_Kbh) + eb);
    __nv_bfloat162* Lp = (__nv_bfloat162*)((which ? g_Vbl : g_Kbl) + eb);
    Hp[0] = *(__nv_bfloat162*)&h01; Hp[1] = *(__nv_bfloat162*)&h23;
    Lp[0] = *(__nv_bfloat162*)&l01; Lp[1] = *(__nv_bfloat162*)&l23;
}

// ---------------------------------------------------------------------------
// mma.sync bf16 split GEMM, 3-stage pipeline, one barrier per k-block,
// fragment double-buffering in the inner loop.
// EPI: 0 = +bias fp32; 1 = +bias+res fp32; 2 = +bias gelu split;
//      3 = QKV: Q cols -> split bf16; K/V cols -> fp32 caches + bf16 splits
// ---------------------------------------------------------------------------
#define TPAD_B   80
#define TILE_B   (128 * TPAD_B)
#define BUF_B    (4 * TILE_B)            // 40960
#define GM_SMEM  (3 * BUF_B)             // 122880

template<int EPI>
__global__ __launch_bounds__(256, 1)
void gemm_mma(const __nv_bfloat16* __restrict__ Ahi, const __nv_bfloat16* __restrict__ Alo,
              const __nv_bfloat16* __restrict__ Bhi, const __nv_bfloat16* __restrict__ Blo,
              const float* __restrict__ bias, const float* __restrict__ Res,
              float* __restrict__ C, __nv_bfloat16* __restrict__ Chi, __nv_bfloat16* __restrict__ Clo,
              float* __restrict__ KC, float* __restrict__ VC,
              int N, int K) {
    extern __shared__ char smc[];
    const uint32_t sb = s2u(smc);
    const int tid  = threadIdx.x;
    const int lane = tid & 31;
    const int wid  = tid >> 5;
    const int wm   = wid >> 2;
    const int wn   = wid & 3;
    const int bm = blockIdx.y * 128;
    const int bn = blockIdx.x * 128;

    const __nv_bfloat16* src0 = Ahi + (size_t)bm * K;
    const __nv_bfloat16* src1 = Alo + (size_t)bm * K;
    const __nv_bfloat16* src2 = Bhi + (size_t)bn * K;
    const __nv_bfloat16* src3 = Blo + (size_t)bn * K;

    const int r0 = tid >> 2,         c0 = tid & 3;
    const int r1 = (tid + 256) >> 2, c1 = tid & 3;

#define PREFETCH(kb, buf)                                                          \
    do {                                                                           \
        const uint32_t db = sb + (buf) * BUF_B;                                    \
        const int ko = (kb) * 32;                                                  \
        cp16(db + 0*TILE_B + r0*TPAD_B + c0*16, (const char*)(src0 + (size_t)r0*K + ko) + c0*16); \
        cp16(db + 0*TILE_B + r1*TPAD_B + c1*16, (const char*)(src0 + (size_t)r1*K + ko) + c1*16); \
        cp16(db + 1*TILE_B + r0*TPAD_B + c0*16, (const char*)(src1 + (size_t)r0*K + ko) + c0*16); \
        cp16(db + 1*TILE_B + r1*TPAD_B + c1*16, (const char*)(src1 + (size_t)r1*K + ko) + c1*16); \
        cp16(db + 2*TILE_B + r0*TPAD_B + c0*16, (const char*)(src2 + (size_t)r0*K + ko) + c0*16); \
        cp16(db + 2*TILE_B + r1*TPAD_B + c1*16, (const char*)(src2 + (size_t)r1*K + ko) + c1*16); \
        cp16(db + 3*TILE_B + r0*TPAD_B + c0*16, (const char*)(src3 + (size_t)r0*K + ko) + c0*16); \
        cp16(db + 3*TILE_B + r1*TPAD_B + c1*16, (const char*)(src3 + (size_t)r1*K + ko) + c1*16); \
        CP_COMMIT();                                                               \
    } while (0)

    float acc[4][4][4];
#pragma unroll
    for (int m = 0; m < 4; m++)
#pragma unroll
        for (int n = 0; n < 4; n++)
#pragma unroll
            for (int i = 0; i < 4; i++) acc[m][n][i] = 0.f;

    const int NKB = K >> 5;
    PREFETCH(0, 0);
    PREFETCH(1, 1);

    const uint32_t aoffb  = (uint32_t)(wm * 64 + (lane & 15)) * TPAD_B + (lane >> 4) * 16;
    const uint32_t boffb  = (uint32_t)(wn * 32 + (lane >> 4) * 8 + (lane & 7)) * TPAD_B
                          + ((lane >> 3) & 1) * 16;

    for (int kb = 0; kb < NKB; kb++) {
        if (kb + 1 < NKB) CP_WAIT(1); else CP_WAIT(0);
        __syncthreads();
        if (kb + 2 < NKB) PREFETCH(kb + 2, (kb + 2) % 3);

        const uint32_t b  = sb + (kb % 3) * BUF_B;
        const uint32_t Ah = b, Al = b + TILE_B, Bh = b + 2 * TILE_B, Bl = b + 3 * TILE_B;

        uint32_t ah[2][4][4], al[2][4][4], bh[2][2][4], bl[2][2][4];
#define LDFRAGS(sl, ks)                                                     \
        do {                                                                \
            const uint32_t ao = aoffb + (ks) * 32, bo = boffb + (ks) * 32;  \
            _Pragma("unroll")                                               \
            for (int m = 0; m < 4; m++) {                                   \
                ldsm4(ah[sl][m], Ah + ao + m * 16 * TPAD_B);                \
                ldsm4(al[sl][m], Al + ao + m * 16 * TPAD_B);                \
            }                                                               \
            _Pragma("unroll")                                               \
            for (int p = 0; p < 2; p++) {                                   \
                ldsm4(bh[sl][p], Bh + bo + p * 16 * TPAD_B);                \
                ldsm4(bl[sl][p], Bl + bo + p * 16 * TPAD_B);                \
            }                                                               \
        } while (0)

        LDFRAGS(0, 0);
#pragma unroll
        for (int ks = 0; ks < 2; ks++) {
            if (ks == 0) LDFRAGS(1, 1);
#pragma unroll
            for (int m = 0; m < 4; m++)
#pragma unroll
                for (int n = 0; n < 4; n++) {
                    const uint32_t* bhn = &bh[ks][n >> 1][(n & 1) * 2];
                    const uint32_t* bln = &bl[ks][n >> 1][(n & 1) * 2];
                    mma16816(acc[m][n], ah[ks][m], bhn);
                    mma16816(acc[m][n], al[ks][m], bhn);
                    mma16816(acc[m][n], ah[ks][m], bln);
                }
        }
#undef LDFRAGS
    }

#pragma unroll
    for (int m = 0; m < 4; m++)
#pragma unroll
        for (int n = 0; n < 4; n++) {
            const int col  = bn + wn * 32 + n * 8 + 2 * (lane & 3);
            const float b0 = bias[col], b1 = bias[col + 1];
#pragma unroll
            for (int half = 0; half < 2; half++) {
                const int row = bm + wm * 64 + m * 16 + (lane >> 2) + half * 8;
                float v0 = acc[m][n][2 * half]     + b0;
                float v1 = acc[m][n][2 * half + 1] + b1;
                if (EPI == 2 || (EPI == 3 && bn < D_MODEL)) {
                    if (EPI == 2) {
                        v0 = 0.5f * v0 * (1.f + erff(v0 * 0.70710678118654752f));
                        v1 = 0.5f * v1 * (1.f + erff(v1 * 0.70710678118654752f));
                    }
                    const int stride = (EPI == 2) ? N : D_MODEL;
                    uint32_t h, l;
                    packsplit(v0, v1, h, l);
                    *(__nv_bfloat162*)(Chi + (size_t)row * stride + col) = *(__nv_bfloat162*)&h;
                    *(__nv_bfloat162*)(Clo + (size_t)row * stride + col) = *(__nv_bfloat162*)&l;
                } else if (EPI == 3) {
                    // K/V columns -> caches at token position TP + t
                    const int which = col >= 2 * D_MODEL;       // 0=K, 1=V
                    const int cc = col - (which ? 2 * D_MODEL : D_MODEL);
                    const int hh = cc >> 6, d = cc & 63;
                    const int bb = row >> 10, t = row & (TC - 1);
                    const size_t crow = ((size_t)(bb * NHEAD + hh)) * TK + TP + t;
                    float2 f2; f2.x = v0; f2.y = v1;
                    *(float2*)((which ? VC : KC) + crow * 64 + d) = f2;
                    uint32_t h, l;
                    packsplit(v0, v1, h, l);
                    *(__nv_bfloat162*)((which ? g_Vbh : g_Kbh) + crow * 64 + d) = *(__nv_bfloat162*)&h;
                    *(__nv_bfloat162*)((which ? g_Vbl : g_Kbl) + crow * 64 + d) = *(__nv_bfloat162*)&l;
                } else {
                    if (EPI == 1) {
                        const float2 rv = *(const float2*)(Res + (size_t)row * N + col);
                        v0 += rv.x; v1 += rv.y;
                    }
                    float2 o2; o2.x = v0; o2.y = v1;
                    *(float2*)(C + (size_t)row * N + col) = o2;
                }
            }
        }
#undef PREFETCH
}

// ---------------------------------------------------------------------------
// Tensor-core flash attention: 128 q-rows per CTA, 8 warps, 3-stage KV pipeline
// ---------------------------------------------------------------------------
#define AQ_TILEB  18432                   // 128 rows * 144 B
#define AKV_TILEB 9216                    // 64 rows * 144 B
#define AKV_STAGE (4 * AKV_TILEB)         // 36864
#define AT_SMEM   (2 * AQ_TILEB + 3 * AKV_STAGE)   // 147456

__global__ __launch_bounds__(256, 1)
void attn_mma(const int* __restrict__ pos_ptr) {
    extern __shared__ char sma[];
    const uint32_t sbase = s2u(sma);
    const int tid = threadIdx.x, lane = tid & 31, w = tid >> 5;
    const int qb = blockIdx.x, bhid = blockIdx.y;
    const int b = bhid >> 4, h = bhid & 15;
    const int q0 = qb * 128;
    const int pos = *pos_ptr;
    const size_t kvbase = (size_t)bhid * TK * HEAD_DIM;
    const uint32_t kvs = sbase + 2 * AQ_TILEB;

#define AT_PRE(kb, bufi)                                                            \
    do {                                                                            \
        const size_t srcb = kvbase + (size_t)(kb) * 64 * 64;                        \
        const uint32_t db = kvs + (bufi) * AKV_STAGE;                               \
        _Pragma("unroll")                                                           \
        for (int t_ = 0; t_ < 2; t_++) {                                            \
            const int i_ = tid + t_ * 256;                                          \
            const int row_ = i_ >> 3; const int ch_ = (i_ & 7) * 16;                \
            const uint32_t doff = (uint32_t)row_ * 144 + ch_;                       \
            const size_t soff = srcb + (size_t)row_ * 64;                           \
            cp16(db + 0 * AKV_TILEB + doff, (const char*)(g_Kbh + soff) + ch_);     \
            cp16(db + 1 * AKV_TILEB + doff, (const char*)(g_Kbl + soff) + ch_);     \
            cp16(db + 2 * AKV_TILEB + doff, (const char*)(g_Vbh + soff) + ch_);     \
            cp16(db + 3 * AKV_TILEB + doff, (const char*)(g_Vbl + soff) + ch_);     \
        }                                                                           \
        CP_COMMIT();                                                                \
    } while (0)

    const int nkb = (pos + q0 + 191) >> 6;

    // prologue: group0 = Q + KV0, group1 = KV1
    {
#pragma unroll
        for (int t_ = 0; t_ < 4; t_++) {
            const int i_ = tid + t_ * 256;
            const int row_ = i_ >> 3; const int ch_ = (i_ & 7) * 16;
            const size_t soff = (size_t)(b * TC + q0 + row_) * D_MODEL + h * HEAD_DIM;
            cp16(sbase + row_ * 144 + ch_,            (const char*)(g_q_hi + soff) + ch_);
            cp16(sbase + AQ_TILEB + row_ * 144 + ch_, (const char*)(g_q_lo + soff) + ch_);
        }
#pragma unroll
        for (int t_ = 0; t_ < 2; t_++) {
            const int i_ = tid + t_ * 256;
            const int row_ = i_ >> 3; const int ch_ = (i_ & 7) * 16;
            const uint32_t doff = (uint32_t)row_ * 144 + ch_;
            const size_t soff = kvbase + (size_t)row_ * 64;
            cp16(kvs + 0 * AKV_TILEB + doff, (const char*)(g_Kbh + soff) + ch_);
            cp16(kvs + 1 * AKV_TILEB + doff, (const char*)(g_Kbl + soff) + ch_);
            cp16(kvs + 2 * AKV_TILEB + doff, (const char*)(g_Vbh + soff) + ch_);
            cp16(kvs + 3 * AKV_TILEB + doff, (const char*)(g_Vbl + soff) + ch_);
        }
        CP_COMMIT();
        if (1 < nkb) AT_PRE(1, 1);
    }

    float oacc[8][4];
#pragma unroll
    for (int nb = 0; nb < 8; nb++)
#pragma unroll
        for (int i = 0; i < 4; i++) oacc[nb][i] = 0.f;
    float m0 = -1e30f, m1 = -1e30f, l0 = 0.f, l1 = 0.f;

    const int r0 = lane >> 2;
    const int lim0 = pos + q0 + w * 16 + r0;
    const int lim1 = lim0 + 8;
    const int warp_lim = pos + q0 + w * 16;

    const uint32_t aoff0 = (uint32_t)(w * 16 + (lane & 15)) * 144 + (lane >> 4) * 16;
    const uint32_t koff0 = (uint32_t)((lane >> 4) * 8 + (lane & 7)) * 144 + ((lane >> 3) & 1) * 16;

    for (int kb = 0; kb < nkb; kb++) {
        if (kb + 1 < nkb) CP_WAIT(1); else CP_WAIT(0);
        __syncthreads();
        if (kb + 2 < nkb) AT_PRE(kb + 2, (kb + 2) % 3);

        const uint32_t bb = kvs + (kb % 3) * AKV_STAGE;
        const uint32_t Kh = bb, Kl = bb + AKV_TILEB, Vh = bb + 2 * AKV_TILEB, Vl = bb + 3 * AKV_TILEB;

        // ---- S = Q K^T ----
        float sacc[8][4];
#pragma unroll
        for (int nb = 0; nb < 8; nb++)
#pragma unroll
            for (int i = 0; i < 4; i++) sacc[nb][i] = 0.f;
#pragma unroll
        for (int ks = 0; ks < 4; ks++) {
            uint32_t ah[4], al[4], kh[4][4], kl[4][4];
            ldsm4(ah, sbase + aoff0 + ks * 32);
            ldsm4(al, sbase + AQ_TILEB + aoff0 + ks * 32);
#pragma unroll
            for (int p = 0; p < 4; p++) {
                ldsm4(kh[p], Kh + koff0 + ks * 32 + p * 16 * 144);
                ldsm4(kl[p], Kl + koff0 + ks * 32 + p * 16 * 144);
            }
#pragma unroll
            for (int nb = 0; nb < 8; nb++) {
                const uint32_t* khn = &kh[nb >> 1][(nb & 1) * 2];
                const uint32_t* kln = &kl[nb >> 1][(nb & 1) * 2];
                mma16816(sacc[nb], ah, khn);
                mma16816(sacc[nb], al, khn);
                mma16816(sacc[nb], ah, kln);
            }
        }

        // ---- scale + mask ----
        const int kstart = kb * 64;
        if (kstart + 63 <= warp_lim) {
#pragma unroll
            for (int nb = 0; nb < 8; nb++)
#pragma unroll
                for (int i = 0; i < 4; i++) sacc[nb][i] *= 0.125f;
        } else {
#pragma unroll
            for (int nb = 0; nb < 8; nb++) {
                const int tok = kstart + nb * 8 + 2 * (lane & 3);
                sacc[nb][0] = (tok     <= lim0) ? sacc[nb][0] * 0.125f : -1e30f;
                sacc[nb][1] = (tok + 1 <= lim0) ? sacc[nb][1] * 0.125f : -1e30f;
                sacc[nb][2] = (tok     <= lim1) ? sacc[nb][2] * 0.125f : -1e30f;
                sacc[nb][3] = (tok + 1 <= lim1) ? sacc[nb][3] * 0.125f : -1e30f;
            }
        }

        // ---- online softmax ----
        float mx0 = -1e30f, mx1 = -1e30f;
#pragma unroll
        for (int nb = 0; nb < 8; nb++) {
            mx0 = fmaxf(mx0, fmaxf(sacc[nb][0], sacc[nb][1]));
            mx1 = fmaxf(mx1, fmaxf(sacc[nb][2], sacc[nb][3]));
        }
        mx0 = fmaxf(mx0, __shfl_xor_sync(0xFFFFFFFFu, mx0, 1));
        mx0 = fmaxf(mx0, __shfl_xor_sync(0xFFFFFFFFu, mx0, 2));
        mx1 = fmaxf(mx1, __shfl_xor_sync(0xFFFFFFFFu, mx1, 1));
        mx1 = fmaxf(mx1, __shfl_xor_sync(0xFFFFFFFFu, mx1, 2));
        const float mn0 = fmaxf(m0, mx0), mn1 = fmaxf(m1, mx1);
        const float al0 = __expf(m0 - mn0), al1 = __expf(m1 - mn1);
        m0 = mn0; m1 = mn1;
        float ls0 = 0.f, ls1 = 0.f;
#pragma unroll
        for (int nb = 0; nb < 8; nb++) {
            sacc[nb][0] = __expf(sacc[nb][0] - mn0);
            sacc[nb][1] = __expf(sacc[nb][1] - mn0);
            sacc[nb][2] = __expf(sacc[nb][2] - mn1);
            sacc[nb][3] = __expf(sacc[nb][3] - mn1);
            ls0 += sacc[nb][0] + sacc[nb][1];
            ls1 += sacc[nb][2] + sacc[nb][3];
        }
        ls0 += __shfl_xor_sync(0xFFFFFFFFu, ls0, 1);
        ls0 += __shfl_xor_sync(0xFFFFFFFFu, ls0, 2);
        ls1 += __shfl_xor_sync(0xFFFFFFFFu, ls1, 1);
        ls1 += __shfl_xor_sync(0xFFFFFFFFu, ls1, 2);
        l0 = l0 * al0 + ls0;
        l1 = l1 * al1 + ls1;
#pragma unroll
        for (int nb = 0; nb < 8; nb++) {
            oacc[nb][0] *= al0; oacc[nb][1] *= al0;
            oacc[nb][2] *= al1; oacc[nb][3] *= al1;
        }

        // ---- O += P V ----
#pragma unroll
        for (int ks = 0; ks < 4; ks++) {
            uint32_t phi[4], plo[4];
            packsplit(sacc[2 * ks][0],     sacc[2 * ks][1],     phi[0], plo[0]);
            packsplit(sacc[2 * ks][2],     sacc[2 * ks][3],     phi[1], plo[1]);
            packsplit(sacc[2 * ks + 1][0], sacc[2 * ks + 1][1], phi[2], plo[2]);
            packsplit(sacc[2 * ks + 1][2], sacc[2 * ks + 1][3], phi[3], plo[3]);
            const uint32_t voff4 = (uint32_t)(ks * 16 + (lane & 15)) * 144 + (lane >> 4) * 16;
            uint32_t vh[4][4], vl[4][4];
#pragma unroll
            for (int p = 0; p < 4; p++) {
                ldsm4t(vh[p], Vh + voff4 + p * 32);
                ldsm4t(vl[p], Vl + voff4 + p * 32);
            }
#pragma unroll
            for (int nb = 0; nb < 8; nb++) {
                const uint32_t* vhn = &vh[nb >> 1][(nb & 1) * 2];
                const uint32_t* vln = &vl[nb >> 1][(nb & 1) * 2];
                mma16816(oacc[nb], phi, vhn);
                mma16816(oacc[nb], plo, vhn);
                mma16816(oacc[nb], phi, vln);
            }
        }
    }

    // ---- epilogue ----
    const float inv0 = 1.f / l0, inv1 = 1.f / l1;
    const int grow0 = b * TC + q0 + w * 16 + r0;
#pragma unroll
    for (int nb = 0; nb < 8; nb++) {
        const int col = h * HEAD_DIM + nb * 8 + 2 * (lane & 3);
        uint32_t hh, ll;
        packsplit(oacc[nb][0] * inv0, oacc[nb][1] * inv0, hh, ll);
        *(__nv_bfloat162*)(g_o_hi + (size_t)grow0 * D_MODEL + col) = *(__nv_bfloat162*)&hh;
        *(__nv_bfloat162*)(g_o_lo + (size_t)grow0 * D_MODEL + col) = *(__nv_bfloat162*)&ll;
        packsplit(oacc[nb][2] * inv1, oacc[nb][3] * inv1, hh, ll);
        *(__nv_bfloat162*)(g_o_hi + (size_t)(grow0 + 8) * D_MODEL + col) = *(__nv_bfloat162*)&hh;
        *(__nv_bfloat162*)(g_o_lo + (size_t)(grow0 + 8) * D_MODEL + col) = *(__nv_bfloat162*)&ll;
    }
#undef AT_PRE
}

// ---------------------------------------------------------------------------
// Launch
// ---------------------------------------------------------------------------
extern "C" void kernel_launch(void* const* d_in, const int* in_sizes, int n_in,
                              void* d_out, int out_size) {
    const float* x    = (const float*)d_in[0];
    const float* Kp   = (const float*)d_in[1];
    const float* Vp   = (const float*)d_in[2];
    const int*   posp = (const int*)  d_in[3];
    const float* wqkv = (const float*)d_in[4];
    const float* bqkv = (const float*)d_in[5];
    const float* wo   = (const float*)d_in[6];
    const float* bo   = (const float*)d_in[7];
    const float* g1   = (const float*)d_in[8];
    const float* be1  = (const float*)d_in[9];
    const float* g2   = (const float*)d_in[10];
    const float* be2  = (const float*)d_in[11];
    const float* w1   = (const float*)d_in[12];
    const float* bf1  = (const float*)d_in[13];
    const float* w2   = (const float*)d_in[14];
    const float* bf2  = (const float*)d_in[15];

    float* out_x = (float*)d_out;
    float* out_K = out_x + (size_t)BATCH * TC * D_MODEL;
    float* out_V = out_K + (size_t)BATCH * NHEAD * TK * HEAD_DIM;

    void* p;
    cudaGetSymbolAddress(&p, g_x1);       float* x1  = (float*)p;
    cudaGetSymbolAddress(&p, g_h_hi);     __nv_bfloat16* hhi = (__nv_bfloat16*)p;
    cudaGetSymbolAddress(&p, g_h_lo);     __nv_bfloat16* hlo = (__nv_bfloat16*)p;
    cudaGetSymbolAddress(&p, g_q_hi);     __nv_bfloat16* qhi = (__nv_bfloat16*)p;
    cudaGetSymbolAddress(&p, g_q_lo);     __nv_bfloat16* qlo = (__nv_bfloat16*)p;
    cudaGetSymbolAddress(&p, g_o_hi);     __nv_bfloat16* ohi = (__nv_bfloat16*)p;
    cudaGetSymbolAddress(&p, g_o_lo);     __nv_bfloat16* olo = (__nv_bfloat16*)p;
    cudaGetSymbolAddress(&p, g_h2_hi);    __nv_bfloat16* h2hi = (__nv_bfloat16*)p;
    cudaGetSymbolAddress(&p, g_h2_lo);    __nv_bfloat16* h2lo = (__nv_bfloat16*)p;
    cudaGetSymbolAddress(&p, g_ff_hi);    __nv_bfloat16* ffhi = (__nv_bfloat16*)p;
    cudaGetSymbolAddress(&p, g_ff_lo);    __nv_bfloat16* fflo = (__nv_bfloat16*)p;
    cudaGetSymbolAddress(&p, g_wqkvT_hi); __nv_bfloat16* wqkvThi = (__nv_bfloat16*)p;
    cudaGetSymbolAddress(&p, g_wqkvT_lo); __nv_bfloat16* wqkvTlo = (__nv_bfloat16*)p;
    cudaGetSymbolAddress(&p, g_woT_hi);   __nv_bfloat16* woThi = (__nv_bfloat16*)p;
    cudaGetSymbolAddress(&p, g_woT_lo);   __nv_bfloat16* woTlo = (__nv_bfloat16*)p;
    cudaGetSymbolAddress(&p, g_w1T_hi);   __nv_bfloat16* w1Thi = (__nv_bfloat16*)p;
    cudaGetSymbolAddress(&p, g_w1T_lo);   __nv_bfloat16* w1Tlo = (__nv_bfloat16*)p;
    cudaGetSymbolAddress(&p, g_w2T_hi);   __nv_bfloat16* w2Thi = (__nv_bfloat16*)p;
    cudaGetSymbolAddress(&p, g_w2T_lo);   __nv_bfloat16* w2Tlo = (__nv_bfloat16*)p;

    cudaFuncSetAttribute(attn_mma, cudaFuncAttributeMaxDynamicSharedMemorySize, AT_SMEM);
    cudaFuncSetAttribute(gemm_mma<0>, cudaFuncAttributeMaxDynamicSharedMemorySize, GM_SMEM);
    cudaFuncSetAttribute(gemm_mma<1>, cudaFuncAttributeMaxDynamicSharedMemorySize, GM_SMEM);
    cudaFuncSetAttribute(gemm_mma<2>, cudaFuncAttributeMaxDynamicSharedMemorySize, GM_SMEM);
    cudaFuncSetAttribute(gemm_mma<3>, cudaFuncAttributeMaxDynamicSharedMemorySize, GM_SMEM);

    // 1) all weight transposes in one launch
    transpose_all<<<12288, 256>>>(wqkv, wo, w1, w2);
    // 2) KV prefix copy (independent of everything downstream of LN)
    kv_prefix<<<8192, 256>>>(Kp, Vp, out_K, out_V);
    // 3) LN1
    ln_split_kernel<<<NROWS, 256>>>(x, g1, be1, hhi, hlo);
    // 4) QKV GEMM: Q -> split bf16; K/V -> caches (fp32 + bf16 splits)
    gemm_mma<3><<<dim3(3 * D_MODEL / 128, NROWS / 128), 256, GM_SMEM>>>(
        hhi, hlo, wqkvThi, wqkvTlo, bqkv, nullptr, nullptr, qhi, qlo, out_K, out_V,
        3 * D_MODEL, D_MODEL);
    // 5) flash attention
    attn_mma<<<dim3(TC / 128, BATCH * NHEAD), 256, AT_SMEM>>>(posp);
    // 6) O-proj + residual -> x1
    gemm_mma<1><<<dim3(D_MODEL / 128, NROWS / 128), 256, GM_SMEM>>>(
        ohi, olo, woThi, woTlo, bo, x, x1, nullptr, nullptr, nullptr, nullptr, D_MODEL, D_MODEL);
    // 7) LN2
    ln_split_kernel<<<NROWS, 256>>>(x1, g2, be2, h2hi, h2lo);
    // 8) FFN1 + GELU
    gemm_mma<2><<<dim3(DIM_FF / 128, NROWS / 128), 256, GM_SMEM>>>(
        h2hi, h2lo, w1Thi, w1Tlo, bf1, nullptr, nullptr, ffhi, fflo, nullptr, nullptr, DIM_FF, D_MODEL);
    // 9) FFN2 + residual -> out_x
    gemm_mma<1><<<dim3(D_MODEL / 128, NROWS / 128), 256, GM_SMEM>>>(
        ffhi, fflo, w2Thi, w2Tlo, bf2, x1, out_x, nullptr, nullptr, nullptr, nullptr, D_MODEL, DIM_FF);
}